// round 1
// baseline (speedup 1.0000x reference)
#include <cuda_runtime.h>
#include <math.h>

// Problem constants
#define BATCH   2
#define NSEQ    2048
#define DMODEL  2048
#define DKV     512
#define NHEADS  16
#define HDIM    128
#define MROWS   (BATCH * NSEQ)   // 4096

// Scratch (device globals: allocation-free rule)
__device__ float g_Q[MROWS * DMODEL];
__device__ float g_K[MROWS * DKV];
__device__ float g_V[MROWS * DKV];
__device__ float g_ctx[MROWS * DMODEL];

// ---------------------------------------------------------------------------
// SGEMM: C[M,N] = A[M,K] @ B[K,N] (+ optional bias[N])
// 128x128 block tile, BK=8, 256 threads, 8x8 microtile per thread.
// M,N divisible by 128; K divisible by 8 (holds for all calls here).
// ---------------------------------------------------------------------------
__global__ __launch_bounds__(256, 2)
void sgemm_kernel(const float* __restrict__ A, const float* __restrict__ Bm,
                  const float* __restrict__ bias, float* __restrict__ C,
                  int M, int N, int K)
{
    __shared__ float As[8][128];   // As[k][m]
    __shared__ float Bs[8][128];   // Bs[k][n]

    const int t  = threadIdx.x;
    const int tx = t & 15;         // 0..15  -> n microtile
    const int ty = t >> 4;         // 0..15  -> m microtile

    const int bn0 = blockIdx.x * 128;
    const int bm0 = blockIdx.y * 128;

    const float* Aptr = A + (size_t)bm0 * K;
    const float* Bptr = Bm + bn0;

    // A-load indices: 128 rows x 8 k, float4 over k
    const int a_m  = t >> 1;
    const int a_k0 = (t & 1) << 2;
    // B-load indices: 8 rows x 128 n, float4 over n
    const int b_k  = t >> 5;
    const int b_n0 = (t & 31) << 2;

    float acc[8][8];
#pragma unroll
    for (int i = 0; i < 8; i++)
#pragma unroll
        for (int j = 0; j < 8; j++) acc[i][j] = 0.f;

    for (int kk = 0; kk < K; kk += 8) {
        // load A tile (transpose to As[k][m])
        float4 av = *(const float4*)&Aptr[(size_t)a_m * K + kk + a_k0];
        As[a_k0 + 0][a_m] = av.x;
        As[a_k0 + 1][a_m] = av.y;
        As[a_k0 + 2][a_m] = av.z;
        As[a_k0 + 3][a_m] = av.w;
        // load B tile
        *(float4*)&Bs[b_k][b_n0] = *(const float4*)&Bptr[(size_t)(kk + b_k) * N + b_n0];
        __syncthreads();

#pragma unroll
        for (int k = 0; k < 8; k++) {
            float ar[8], br[8];
            *(float4*)&ar[0] = *(const float4*)&As[k][ty * 8];
            *(float4*)&ar[4] = *(const float4*)&As[k][ty * 8 + 4];
            *(float4*)&br[0] = *(const float4*)&Bs[k][tx * 8];
            *(float4*)&br[4] = *(const float4*)&Bs[k][tx * 8 + 4];
#pragma unroll
            for (int i = 0; i < 8; i++)
#pragma unroll
                for (int j = 0; j < 8; j++)
                    acc[i][j] = fmaf(ar[i], br[j], acc[i][j]);
        }
        __syncthreads();
    }

    // epilogue
    const int cn0 = bn0 + tx * 8;
    float bsv[8];
    if (bias) {
#pragma unroll
        for (int j = 0; j < 8; j++) bsv[j] = bias[cn0 + j];
    } else {
#pragma unroll
        for (int j = 0; j < 8; j++) bsv[j] = 0.f;
    }
#pragma unroll
    for (int i = 0; i < 8; i++) {
        float* crow = C + (size_t)(bm0 + ty * 8 + i) * N + cn0;
        float4 v0, v1;
        v0.x = acc[i][0] + bsv[0]; v0.y = acc[i][1] + bsv[1];
        v0.z = acc[i][2] + bsv[2]; v0.w = acc[i][3] + bsv[3];
        v1.x = acc[i][4] + bsv[4]; v1.y = acc[i][5] + bsv[5];
        v1.z = acc[i][6] + bsv[6]; v1.w = acc[i][7] + bsv[7];
        *(float4*)&crow[0] = v0;
        *(float4*)&crow[4] = v1;
    }
}

// ---------------------------------------------------------------------------
// Flash attention (causal), fp32.
// Grid: (n/64 row tiles, 16 heads, 2 batches). Block: 256 threads.
// Br = Bc = 64. Head h reads Q cols h*128, K/V head g = h/4 cols g*128.
// S tile 64x64: 16x16 threads x 4x4. O tile 64x128: 4 rows x 8 cols/thread.
// ---------------------------------------------------------------------------
#define QS_STRIDE 132
#define PS_STRIDE 68
#define FLASH_SMEM ((3 * 64 * QS_STRIDE + 64 * PS_STRIDE) * 4)

__global__ __launch_bounds__(256, 1)
void flash_kernel(const float* __restrict__ Q, const float* __restrict__ K,
                  const float* __restrict__ V, float* __restrict__ ctx)
{
    extern __shared__ float sm[];
    float* Qs = sm;                        // [64][132]
    float* Ks = Qs + 64 * QS_STRIDE;       // [64][132]
    float* Vs = Ks + 64 * QS_STRIDE;       // [64][132]
    float* Ps = Vs + 64 * QS_STRIDE;       // [64][68]

    const int t  = threadIdx.x;
    const int tx = t & 15;
    const int ty = t >> 4;
    const int jr = blockIdx.x;
    const int h  = blockIdx.y;
    const int b  = blockIdx.z;
    const int g  = h >> 2;
    const int qr0 = jr * 64;
    const float scale = 0.08838834764831845f;  // 1/sqrt(128)

    const float* Qbase = Q + (size_t)b * NSEQ * DMODEL + h * HDIM;
    const float* Kbase = K + (size_t)b * NSEQ * DKV + g * HDIM;
    const float* Vbase = V + (size_t)b * NSEQ * DKV + g * HDIM;

    // Load + scale Q tile
    for (int i = t; i < 64 * 32; i += 256) {
        int r = i >> 5, c4 = (i & 31) << 2;
        float4 v = *(const float4*)&Qbase[(size_t)(qr0 + r) * DMODEL + c4];
        v.x *= scale; v.y *= scale; v.z *= scale; v.w *= scale;
        *(float4*)&Qs[r * QS_STRIDE + c4] = v;
    }

    float m_i[4], l_i[4], O[4][8];
#pragma unroll
    for (int i = 0; i < 4; i++) {
        m_i[i] = -INFINITY; l_i[i] = 0.f;
#pragma unroll
        for (int c = 0; c < 8; c++) O[i][c] = 0.f;
    }

    const int r0 = ty * 4;
    const int c0 = tx * 4;

    for (int jc = 0; jc <= jr; jc++) {
        const int kc0 = jc * 64;
        __syncthreads();   // prior-iter P@V done before tiles are overwritten
        for (int i = t; i < 64 * 32; i += 256) {
            int r = i >> 5, c4 = (i & 31) << 2;
            *(float4*)&Ks[r * QS_STRIDE + c4] =
                *(const float4*)&Kbase[(size_t)(kc0 + r) * DKV + c4];
            *(float4*)&Vs[r * QS_STRIDE + c4] =
                *(const float4*)&Vbase[(size_t)(kc0 + r) * DKV + c4];
        }
        __syncthreads();

        // S = Qs @ Ks^T (4x4 per thread)
        float S[4][4];
#pragma unroll
        for (int i = 0; i < 4; i++)
#pragma unroll
            for (int j = 0; j < 4; j++) S[i][j] = 0.f;

        for (int k4 = 0; k4 < 128; k4 += 4) {
            float4 qv[4], kv[4];
#pragma unroll
            for (int i = 0; i < 4; i++)
                qv[i] = *(const float4*)&Qs[(r0 + i) * QS_STRIDE + k4];
#pragma unroll
            for (int j = 0; j < 4; j++)
                kv[j] = *(const float4*)&Ks[(c0 + j) * QS_STRIDE + k4];
#pragma unroll
            for (int i = 0; i < 4; i++)
#pragma unroll
                for (int j = 0; j < 4; j++) {
                    S[i][j] = fmaf(qv[i].x, kv[j].x, S[i][j]);
                    S[i][j] = fmaf(qv[i].y, kv[j].y, S[i][j]);
                    S[i][j] = fmaf(qv[i].z, kv[j].z, S[i][j]);
                    S[i][j] = fmaf(qv[i].w, kv[j].w, S[i][j]);
                }
        }

        // causal mask on diagonal tile
        if (jc == jr) {
#pragma unroll
            for (int i = 0; i < 4; i++)
#pragma unroll
                for (int j = 0; j < 4; j++)
                    if (kc0 + c0 + j > qr0 + r0 + i) S[i][j] = -INFINITY;
        }

        // online softmax update
#pragma unroll
        for (int i = 0; i < 4; i++) {
            float mx = fmaxf(fmaxf(S[i][0], S[i][1]), fmaxf(S[i][2], S[i][3]));
#pragma unroll
            for (int d = 1; d < 16; d <<= 1)
                mx = fmaxf(mx, __shfl_xor_sync(0xffffffffu, mx, d));
            float m_new = fmaxf(m_i[i], mx);
            float alpha = __expf(m_i[i] - m_new);
            float p0 = __expf(S[i][0] - m_new);
            float p1 = __expf(S[i][1] - m_new);
            float p2 = __expf(S[i][2] - m_new);
            float p3 = __expf(S[i][3] - m_new);
            float rs = p0 + p1 + p2 + p3;
#pragma unroll
            for (int d = 1; d < 16; d <<= 1)
                rs += __shfl_xor_sync(0xffffffffu, rs, d);
            l_i[i] = l_i[i] * alpha + rs;
            m_i[i] = m_new;
#pragma unroll
            for (int c = 0; c < 8; c++) O[i][c] *= alpha;
            float4 pv = make_float4(p0, p1, p2, p3);
            *(float4*)&Ps[(r0 + i) * PS_STRIDE + c0] = pv;
        }
        __syncthreads();

        // O += P @ V  (cols tx*8 .. tx*8+7)
        const int oc0 = tx * 8;
#pragma unroll 4
        for (int k = 0; k < 64; k++) {
            float p0 = Ps[(r0 + 0) * PS_STRIDE + k];
            float p1 = Ps[(r0 + 1) * PS_STRIDE + k];
            float p2 = Ps[(r0 + 2) * PS_STRIDE + k];
            float p3 = Ps[(r0 + 3) * PS_STRIDE + k];
            float4 v0 = *(const float4*)&Vs[k * QS_STRIDE + oc0];
            float4 v1 = *(const float4*)&Vs[k * QS_STRIDE + oc0 + 4];
            O[0][0] = fmaf(p0, v0.x, O[0][0]); O[0][1] = fmaf(p0, v0.y, O[0][1]);
            O[0][2] = fmaf(p0, v0.z, O[0][2]); O[0][3] = fmaf(p0, v0.w, O[0][3]);
            O[0][4] = fmaf(p0, v1.x, O[0][4]); O[0][5] = fmaf(p0, v1.y, O[0][5]);
            O[0][6] = fmaf(p0, v1.z, O[0][6]); O[0][7] = fmaf(p0, v1.w, O[0][7]);
            O[1][0] = fmaf(p1, v0.x, O[1][0]); O[1][1] = fmaf(p1, v0.y, O[1][1]);
            O[1][2] = fmaf(p1, v0.z, O[1][2]); O[1][3] = fmaf(p1, v0.w, O[1][3]);
            O[1][4] = fmaf(p1, v1.x, O[1][4]); O[1][5] = fmaf(p1, v1.y, O[1][5]);
            O[1][6] = fmaf(p1, v1.z, O[1][6]); O[1][7] = fmaf(p1, v1.w, O[1][7]);
            O[2][0] = fmaf(p2, v0.x, O[2][0]); O[2][1] = fmaf(p2, v0.y, O[2][1]);
            O[2][2] = fmaf(p2, v0.z, O[2][2]); O[2][3] = fmaf(p2, v0.w, O[2][3]);
            O[2][4] = fmaf(p2, v1.x, O[2][4]); O[2][5] = fmaf(p2, v1.y, O[2][5]);
            O[2][6] = fmaf(p2, v1.z, O[2][6]); O[2][7] = fmaf(p2, v1.w, O[2][7]);
            O[3][0] = fmaf(p3, v0.x, O[3][0]); O[3][1] = fmaf(p3, v0.y, O[3][1]);
            O[3][2] = fmaf(p3, v0.z, O[3][2]); O[3][3] = fmaf(p3, v0.w, O[3][3]);
            O[3][4] = fmaf(p3, v1.x, O[3][4]); O[3][5] = fmaf(p3, v1.y, O[3][5]);
            O[3][6] = fmaf(p3, v1.z, O[3][6]); O[3][7] = fmaf(p3, v1.w, O[3][7]);
        }
    }

    // write ctx[b, q, h*128 + cc] (head-major within d_model, matching reshape)
    float* Cb = ctx + (size_t)b * NSEQ * DMODEL + h * HDIM;
    const int oc0 = tx * 8;
#pragma unroll
    for (int i = 0; i < 4; i++) {
        float inv = 1.f / l_i[i];
        float4 v0, v1;
        v0.x = O[i][0] * inv; v0.y = O[i][1] * inv;
        v0.z = O[i][2] * inv; v0.w = O[i][3] * inv;
        v1.x = O[i][4] * inv; v1.y = O[i][5] * inv;
        v1.z = O[i][6] * inv; v1.w = O[i][7] * inv;
        float* row = Cb + (size_t)(qr0 + r0 + i) * DMODEL + oc0;
        *(float4*)&row[0] = v0;
        *(float4*)&row[4] = v1;
    }
}

// ---------------------------------------------------------------------------
extern "C" void kernel_launch(void* const* d_in, const int* in_sizes, int n_in,
                              void* d_out, int out_size)
{
    (void)in_sizes; (void)n_in; (void)out_size;
    const float* x  = (const float*)d_in[0];
    const float* Wq = (const float*)d_in[1];
    const float* Wk = (const float*)d_in[2];
    const float* Wv = (const float*)d_in[3];
    const float* Wo = (const float*)d_in[4];
    const float* bo = (const float*)d_in[5];
    float* out = (float*)d_out;

    float *Qb, *Kb, *Vb, *Cb;
    cudaGetSymbolAddress((void**)&Qb, g_Q);
    cudaGetSymbolAddress((void**)&Kb, g_K);
    cudaGetSymbolAddress((void**)&Vb, g_V);
    cudaGetSymbolAddress((void**)&Cb, g_ctx);

    // Projections
    sgemm_kernel<<<dim3(DMODEL / 128, MROWS / 128), 256>>>(x, Wq, nullptr, Qb,
                                                           MROWS, DMODEL, DMODEL);
    sgemm_kernel<<<dim3(DKV / 128, MROWS / 128), 256>>>(x, Wk, nullptr, Kb,
                                                        MROWS, DKV, DMODEL);
    sgemm_kernel<<<dim3(DKV / 128, MROWS / 128), 256>>>(x, Wv, nullptr, Vb,
                                                        MROWS, DKV, DMODEL);

    // Attention
    cudaFuncSetAttribute(flash_kernel, cudaFuncAttributeMaxDynamicSharedMemorySize,
                         FLASH_SMEM);
    flash_kernel<<<dim3(NSEQ / 64, NHEADS, BATCH), 256, FLASH_SMEM>>>(Qb, Kb, Vb, Cb);

    // Output projection + bias
    sgemm_kernel<<<dim3(DMODEL / 128, MROWS / 128), 256>>>(Cb, Wo, bo, out,
                                                           MROWS, DMODEL, DMODEL);
}

// round 3
// speedup vs baseline: 1.5752x; 1.5752x over previous
#include <cuda_runtime.h>
#include <cuda_bf16.h>
#include <math.h>
#include <stdint.h>

// ---------------- problem constants ----------------
#define BATCH   2
#define NSEQ    2048
#define DMODEL  2048
#define KVW     1024          // merged K|V width
#define NHEADS  16
#define HDIM    128
#define MROWS   4096
#define K2      2048          // original inner dim
#define KX      6144          // split inner dim (hi | lo | hi)
#define NCH     (KX / 64)     // 96 K-chunks of 64

// ---------------- scratch (device globals; no runtime alloc) ----------------
__device__ float g_Q[(size_t)MROWS * DMODEL];
__device__ float g_KV[(size_t)MROWS * KVW];
__device__ float g_ctx[(size_t)MROWS * DMODEL];
__device__ __nv_bfloat16 g_xs[(size_t)MROWS * KX];
__device__ __nv_bfloat16 g_cs[(size_t)MROWS * KX];
__device__ __nv_bfloat16 g_Wqs[(size_t)DMODEL * KX];
__device__ __nv_bfloat16 g_Wkvs[(size_t)KVW * KX];
__device__ __nv_bfloat16 g_Wos[(size_t)DMODEL * KX];

// ---------------- helpers ----------------
__device__ __forceinline__ uint32_t smem_u32(const void* p) {
    uint32_t a;
    asm("{ .reg .u64 t; cvta.to.shared.u64 t, %1; cvt.u32.u64 %0, t; }" : "=r"(a) : "l"(p));
    return a;
}
__device__ __forceinline__ void cp16(uint32_t dst, const void* src) {
    asm volatile("cp.async.cg.shared.global [%0], [%1], 16;" :: "r"(dst), "l"(src));
}
#define CP_COMMIT() asm volatile("cp.async.commit_group;" ::: "memory")

__device__ __forceinline__ void ldmat4(uint32_t* r, uint32_t addr) {
    asm volatile("ldmatrix.sync.aligned.m8n8.x4.shared.b16 {%0,%1,%2,%3}, [%4];"
                 : "=r"(r[0]), "=r"(r[1]), "=r"(r[2]), "=r"(r[3]) : "r"(addr));
}
__device__ __forceinline__ void mma16816(float* d, const uint32_t* a, const uint32_t* b) {
    asm volatile("mma.sync.aligned.m16n8k16.row.col.f32.bf16.bf16.f32 "
                 "{%0,%1,%2,%3}, {%4,%5,%6,%7}, {%8,%9}, {%0,%1,%2,%3};"
                 : "+f"(d[0]), "+f"(d[1]), "+f"(d[2]), "+f"(d[3])
                 : "r"(a[0]), "r"(a[1]), "r"(a[2]), "r"(a[3]), "r"(b[0]), "r"(b[1]));
}

// ---------------------------------------------------------------------------
// Split conversion kernels (fp32 -> bf16 [hi | lo | hi] along K)
// ---------------------------------------------------------------------------
__global__ void split_act(const float* __restrict__ src, __nv_bfloat16* __restrict__ dst,
                          int total4)
{
    int i = blockIdx.x * 256 + threadIdx.x;
    if (i >= total4) return;
    int m = i >> 9;                 // 512 float4 per row (K2=2048)
    int c = (i & 511) << 2;
    float4 v = *(const float4*)&src[(size_t)m * K2 + c];
    __nv_bfloat16 h0 = __float2bfloat16(v.x), h1 = __float2bfloat16(v.y);
    __nv_bfloat16 h2 = __float2bfloat16(v.z), h3 = __float2bfloat16(v.w);
    __nv_bfloat16 l0 = __float2bfloat16(v.x - __bfloat162float(h0));
    __nv_bfloat16 l1 = __float2bfloat16(v.y - __bfloat162float(h1));
    __nv_bfloat16 l2 = __float2bfloat16(v.z - __bfloat162float(h2));
    __nv_bfloat16 l3 = __float2bfloat16(v.w - __bfloat162float(h3));
    __nv_bfloat162 hA = __nv_bfloat162(h0, h1), hB = __nv_bfloat162(h2, h3);
    __nv_bfloat162 lA = __nv_bfloat162(l0, l1), lB = __nv_bfloat162(l2, l3);
    __nv_bfloat162* p0 = (__nv_bfloat162*)&dst[(size_t)m * KX + c];
    __nv_bfloat162* p1 = (__nv_bfloat162*)&dst[(size_t)m * KX + K2 + c];
    __nv_bfloat162* p2 = (__nv_bfloat162*)&dst[(size_t)m * KX + 2 * K2 + c];
    p0[0] = hA; p0[1] = hB;        // block 0: hi
    p1[0] = lA; p1[1] = lB;        // block 1: lo
    p2[0] = hA; p2[1] = hB;        // block 2: hi
}

// W [K2 x N] -> dst rows [rowoff+n][ hi | hi | lo ] (transposed, width KX)
__global__ void split_wt(const float* __restrict__ W, __nv_bfloat16* __restrict__ dst,
                         int N, int rowoff)
{
    __shared__ float tile[32][33];
    int n0 = blockIdx.x * 32, k0 = blockIdx.y * 32;
    int tx = threadIdx.x, ty = threadIdx.y;   // 32 x 8
#pragma unroll
    for (int j = 0; j < 32; j += 8)
        tile[ty + j][tx] = W[(size_t)(k0 + ty + j) * N + n0 + tx];
    __syncthreads();
#pragma unroll
    for (int j = 0; j < 32; j += 8) {
        int n = n0 + ty + j;
        int k = k0 + tx;
        float v = tile[tx][ty + j];
        __nv_bfloat16 hi = __float2bfloat16(v);
        __nv_bfloat16 lo = __float2bfloat16(v - __bfloat162float(hi));
        size_t base = (size_t)(rowoff + n) * KX;
        dst[base + k]          = hi;   // pairs with A-hi
        dst[base + K2 + k]     = hi;   // pairs with A-lo
        dst[base + 2 * K2 + k] = lo;   // pairs with A-hi
    }
}

// ---------------------------------------------------------------------------
// bf16 GEMM via mma.sync (m16n8k16): C[M,Nt] = A'[M,KX] @ B'[Nt,KX]^T (+bias)
// CTA 128x128, BK=64 (128B rows, SW128 swizzle), 3-stage cp.async pipeline.
// 8 warps in 4(m) x 2(n); warp tile 32x64.
// ---------------------------------------------------------------------------
#define STAGE_BYTES 32768       // A 16KB + B 16KB
#define GSMEM (3 * STAGE_BYTES)

__global__ void __launch_bounds__(256)
gemm_mma(const __nv_bfloat16* __restrict__ A, const __nv_bfloat16* __restrict__ B,
         const float* __restrict__ bias, float* __restrict__ C, int Nt)
{
    extern __shared__ char sm[];
    const uint32_t sb = smem_u32(sm);
    const int tid = threadIdx.x;
    const int warp = tid >> 5, lane = tid & 31;
    const int wm = warp >> 1;          // 0..3 (m)
    const int wn = warp & 1;           // 0..1 (n)
    const int bm0 = blockIdx.y * 128;
    const int bn0 = blockIdx.x * 128;

    const __nv_bfloat16* Ab = A + (size_t)bm0 * KX;
    const __nv_bfloat16* Bb = B + (size_t)bn0 * KX;

    // cp.async per-thread chunk schedule: 1024 chunks (A)+(B) each, 16B
    // ldmatrix source geometry (within 128x128B tile):
    const int a_row0 = wm * 32 + (lane & 15);
    const uint32_t a_half = (uint32_t)((lane >> 4) << 4);         // 0 / 16 bytes
    const uint32_t a_xr = (uint32_t)((a_row0 & 7) << 4);
    uint32_t a_rb[2];
    a_rb[0] = (uint32_t)(a_row0 * 128);
    a_rb[1] = (uint32_t)((a_row0 + 16) * 128);

    const int b_row0 = wn * 64 + (lane & 7) + ((lane >> 4) << 3); // n within tile
    const uint32_t b_half = (uint32_t)(((lane >> 3) & 1) << 4);
    const uint32_t b_xr = (uint32_t)((b_row0 & 7) << 4);
    uint32_t b_rb[4];
#pragma unroll
    for (int p = 0; p < 4; p++) b_rb[p] = (uint32_t)((b_row0 + p * 16) * 128);

    float acc[2][8][4];
#pragma unroll
    for (int mf = 0; mf < 2; mf++)
#pragma unroll
        for (int nf = 0; nf < 8; nf++)
#pragma unroll
            for (int j = 0; j < 4; j++) acc[mf][nf][j] = 0.f;

    // stage loader
    auto load_stage = [&](int s, int kc) {
        uint32_t abase = sb + (uint32_t)s * STAGE_BYTES;
        uint32_t bbase = abase + 16384;
        const __nv_bfloat16* ak = Ab + (size_t)kc * 64;
        const __nv_bfloat16* bk = Bb + (size_t)kc * 64;
#pragma unroll
        for (int c = tid; c < 1024; c += 256) {
            int r = c >> 3, sg = c & 7;
            uint32_t off = (uint32_t)(r * 128 + sg * 16);
            uint32_t sw = off ^ ((off >> 3) & 0x70);
            cp16(abase + sw, (const void*)(ak + (size_t)r * KX + sg * 8));
            cp16(bbase + sw, (const void*)(bk + (size_t)r * KX + sg * 8));
        }
        CP_COMMIT();
    };

    load_stage(0, 0);
    load_stage(1, 1);

    for (int i = 0; i < NCH; i++) {
        const int s = i % 3;
        if (i + 2 < NCH) {
            load_stage((i + 2) % 3, i + 2);
            asm volatile("cp.async.wait_group 2;" ::: "memory");
        } else if (i + 2 == NCH) {
            asm volatile("cp.async.wait_group 1;" ::: "memory");
        } else {
            asm volatile("cp.async.wait_group 0;" ::: "memory");
        }
        __syncthreads();

        const uint32_t abase = sb + (uint32_t)s * STAGE_BYTES;
        const uint32_t bbase = abase + 16384;
#pragma unroll
        for (int ks = 0; ks < 4; ks++) {
            uint32_t afrag[2][4];
            uint32_t bfrag[8][2];
#pragma unroll
            for (int mf = 0; mf < 2; mf++)
                ldmat4(afrag[mf], abase + a_rb[mf] + (((uint32_t)(ks * 32) + a_half) ^ a_xr));
#pragma unroll
            for (int p = 0; p < 4; p++) {
                uint32_t r4[4];
                ldmat4(r4, bbase + b_rb[p] + (((uint32_t)(ks * 32) + b_half) ^ b_xr));
                bfrag[2 * p][0] = r4[0]; bfrag[2 * p][1] = r4[1];
                bfrag[2 * p + 1][0] = r4[2]; bfrag[2 * p + 1][1] = r4[3];
            }
#pragma unroll
            for (int mf = 0; mf < 2; mf++)
#pragma unroll
                for (int nf = 0; nf < 8; nf++)
                    mma16816(acc[mf][nf], afrag[mf], bfrag[nf]);
        }
        __syncthreads();
    }

    // epilogue
    const int m_base = bm0 + wm * 32;
    const int n_base = bn0 + wn * 64;
    const int rl = lane >> 2;            // 0..7
    const int cl = (lane & 3) * 2;
#pragma unroll
    for (int mf = 0; mf < 2; mf++) {
#pragma unroll
        for (int nf = 0; nf < 8; nf++) {
            int col = n_base + nf * 8 + cl;
            float b0 = 0.f, b1 = 0.f;
            if (bias) { b0 = bias[col]; b1 = bias[col + 1]; }
            int r0 = m_base + mf * 16 + rl;
            float2 v0 = make_float2(acc[mf][nf][0] + b0, acc[mf][nf][1] + b1);
            float2 v1 = make_float2(acc[mf][nf][2] + b0, acc[mf][nf][3] + b1);
            *(float2*)&C[(size_t)r0 * Nt + col] = v0;
            *(float2*)&C[(size_t)(r0 + 8) * Nt + col] = v1;
        }
    }
}

// ---------------------------------------------------------------------------
// Flash attention (causal), fp32 (unchanged; merged K|V buffer, stride 1024)
// ---------------------------------------------------------------------------
#define QS_STRIDE 132
#define PS_STRIDE 68
#define FLASH_SMEM ((3 * 64 * QS_STRIDE + 64 * PS_STRIDE) * 4)

__global__ __launch_bounds__(256, 1)
void flash_kernel(const float* __restrict__ Q, const float* __restrict__ KV,
                  float* __restrict__ ctx)
{
    extern __shared__ float smf[];
    float* Qs = smf;
    float* Ks = Qs + 64 * QS_STRIDE;
    float* Vs = Ks + 64 * QS_STRIDE;
    float* Ps = Vs + 64 * QS_STRIDE;

    const int t  = threadIdx.x;
    const int tx = t & 15;
    const int ty = t >> 4;
    const int jr = blockIdx.x;
    const int h  = blockIdx.y;
    const int b  = blockIdx.z;
    const int g  = h >> 2;
    const int qr0 = jr * 64;
    const float scale = 0.08838834764831845f;

    const float* Qbase = Q + (size_t)b * NSEQ * DMODEL + h * HDIM;
    const float* Kbase = KV + (size_t)b * NSEQ * KVW + g * HDIM;
    const float* Vbase = Kbase + 512;

    for (int i = t; i < 64 * 32; i += 256) {
        int r = i >> 5, c4 = (i & 31) << 2;
        float4 v = *(const float4*)&Qbase[(size_t)(qr0 + r) * DMODEL + c4];
        v.x *= scale; v.y *= scale; v.z *= scale; v.w *= scale;
        *(float4*)&Qs[r * QS_STRIDE + c4] = v;
    }

    float m_i[4], l_i[4], O[4][8];
#pragma unroll
    for (int i = 0; i < 4; i++) {
        m_i[i] = -INFINITY; l_i[i] = 0.f;
#pragma unroll
        for (int c = 0; c < 8; c++) O[i][c] = 0.f;
    }

    const int r0 = ty * 4;
    const int c0 = tx * 4;

    for (int jc = 0; jc <= jr; jc++) {
        const int kc0 = jc * 64;
        __syncthreads();
        for (int i = t; i < 64 * 32; i += 256) {
            int r = i >> 5, c4 = (i & 31) << 2;
            *(float4*)&Ks[r * QS_STRIDE + c4] =
                *(const float4*)&Kbase[(size_t)(kc0 + r) * KVW + c4];
            *(float4*)&Vs[r * QS_STRIDE + c4] =
                *(const float4*)&Vbase[(size_t)(kc0 + r) * KVW + c4];
        }
        __syncthreads();

        float S[4][4];
#pragma unroll
        for (int i = 0; i < 4; i++)
#pragma unroll
            for (int j = 0; j < 4; j++) S[i][j] = 0.f;

        for (int k4 = 0; k4 < 128; k4 += 4) {
            float4 qv[4], kv[4];
#pragma unroll
            for (int i = 0; i < 4; i++)
                qv[i] = *(const float4*)&Qs[(r0 + i) * QS_STRIDE + k4];
#pragma unroll
            for (int j = 0; j < 4; j++)
                kv[j] = *(const float4*)&Ks[(c0 + j) * QS_STRIDE + k4];
#pragma unroll
            for (int i = 0; i < 4; i++)
#pragma unroll
                for (int j = 0; j < 4; j++) {
                    S[i][j] = fmaf(qv[i].x, kv[j].x, S[i][j]);
                    S[i][j] = fmaf(qv[i].y, kv[j].y, S[i][j]);
                    S[i][j] = fmaf(qv[i].z, kv[j].z, S[i][j]);
                    S[i][j] = fmaf(qv[i].w, kv[j].w, S[i][j]);
                }
        }

        if (jc == jr) {
#pragma unroll
            for (int i = 0; i < 4; i++)
#pragma unroll
                for (int j = 0; j < 4; j++)
                    if (kc0 + c0 + j > qr0 + r0 + i) S[i][j] = -INFINITY;
        }

#pragma unroll
        for (int i = 0; i < 4; i++) {
            float mx = fmaxf(fmaxf(S[i][0], S[i][1]), fmaxf(S[i][2], S[i][3]));
#pragma unroll
            for (int d = 1; d < 16; d <<= 1)
                mx = fmaxf(mx, __shfl_xor_sync(0xffffffffu, mx, d));
            float m_new = fmaxf(m_i[i], mx);
            float alpha = __expf(m_i[i] - m_new);
            float p0 = __expf(S[i][0] - m_new);
            float p1 = __expf(S[i][1] - m_new);
            float p2 = __expf(S[i][2] - m_new);
            float p3 = __expf(S[i][3] - m_new);
            float rs = p0 + p1 + p2 + p3;
#pragma unroll
            for (int d = 1; d < 16; d <<= 1)
                rs += __shfl_xor_sync(0xffffffffu, rs, d);
            l_i[i] = l_i[i] * alpha + rs;
            m_i[i] = m_new;
#pragma unroll
            for (int c = 0; c < 8; c++) O[i][c] *= alpha;
            *(float4*)&Ps[(r0 + i) * PS_STRIDE + c0] = make_float4(p0, p1, p2, p3);
        }
        __syncthreads();

        const int oc0 = tx * 8;
#pragma unroll 4
        for (int k = 0; k < 64; k++) {
            float p0 = Ps[(r0 + 0) * PS_STRIDE + k];
            float p1 = Ps[(r0 + 1) * PS_STRIDE + k];
            float p2 = Ps[(r0 + 2) * PS_STRIDE + k];
            float p3 = Ps[(r0 + 3) * PS_STRIDE + k];
            float4 v0 = *(const float4*)&Vs[k * QS_STRIDE + oc0];
            float4 v1 = *(const float4*)&Vs[k * QS_STRIDE + oc0 + 4];
            O[0][0] = fmaf(p0, v0.x, O[0][0]); O[0][1] = fmaf(p0, v0.y, O[0][1]);
            O[0][2] = fmaf(p0, v0.z, O[0][2]); O[0][3] = fmaf(p0, v0.w, O[0][3]);
            O[0][4] = fmaf(p0, v1.x, O[0][4]); O[0][5] = fmaf(p0, v1.y, O[0][5]);
            O[0][6] = fmaf(p0, v1.z, O[0][6]); O[0][7] = fmaf(p0, v1.w, O[0][7]);
            O[1][0] = fmaf(p1, v0.x, O[1][0]); O[1][1] = fmaf(p1, v0.y, O[1][1]);
            O[1][2] = fmaf(p1, v0.z, O[1][2]); O[1][3] = fmaf(p1, v0.w, O[1][3]);
            O[1][4] = fmaf(p1, v1.x, O[1][4]); O[1][5] = fmaf(p1, v1.y, O[1][5]);
            O[1][6] = fmaf(p1, v1.z, O[1][6]); O[1][7] = fmaf(p1, v1.w, O[1][7]);
            O[2][0] = fmaf(p2, v0.x, O[2][0]); O[2][1] = fmaf(p2, v0.y, O[2][1]);
            O[2][2] = fmaf(p2, v0.z, O[2][2]); O[2][3] = fmaf(p2, v0.w, O[2][3]);
            O[2][4] = fmaf(p2, v1.x, O[2][4]); O[2][5] = fmaf(p2, v1.y, O[2][5]);
            O[2][6] = fmaf(p2, v1.z, O[2][6]); O[2][7] = fmaf(p2, v1.w, O[2][7]);
            O[3][0] = fmaf(p3, v0.x, O[3][0]); O[3][1] = fmaf(p3, v0.y, O[3][1]);
            O[3][2] = fmaf(p3, v0.z, O[3][2]); O[3][3] = fmaf(p3, v0.w, O[3][3]);
            O[3][4] = fmaf(p3, v1.x, O[3][4]); O[3][5] = fmaf(p3, v1.y, O[3][5]);
            O[3][6] = fmaf(p3, v1.z, O[3][6]); O[3][7] = fmaf(p3, v1.w, O[3][7]);
        }
    }

    float* Cb = ctx + (size_t)b * NSEQ * DMODEL + h * HDIM;
    const int oc0 = tx * 8;
#pragma unroll
    for (int i = 0; i < 4; i++) {
        float inv = 1.f / l_i[i];
        float4 v0, v1;
        v0.x = O[i][0] * inv; v0.y = O[i][1] * inv;
        v0.z = O[i][2] * inv; v0.w = O[i][3] * inv;
        v1.x = O[i][4] * inv; v1.y = O[i][5] * inv;
        v1.z = O[i][6] * inv; v1.w = O[i][7] * inv;
        float* row = Cb + (size_t)(qr0 + r0 + i) * DMODEL + oc0;
        *(float4*)&row[0] = v0;
        *(float4*)&row[4] = v1;
    }
}

// ---------------------------------------------------------------------------
extern "C" void kernel_launch(void* const* d_in, const int* in_sizes, int n_in,
                              void* d_out, int out_size)
{
    (void)in_sizes; (void)n_in; (void)out_size;
    const float* x  = (const float*)d_in[0];
    const float* Wq = (const float*)d_in[1];
    const float* Wk = (const float*)d_in[2];
    const float* Wv = (const float*)d_in[3];
    const float* Wo = (const float*)d_in[4];
    const float* bo = (const float*)d_in[5];
    float* out = (float*)d_out;

    float *Qb, *KVb, *Cb;
    __nv_bfloat16 *xs, *cs, *Wqs, *Wkvs, *Wos;
    cudaGetSymbolAddress((void**)&Qb, g_Q);
    cudaGetSymbolAddress((void**)&KVb, g_KV);
    cudaGetSymbolAddress((void**)&Cb, g_ctx);
    cudaGetSymbolAddress((void**)&xs, g_xs);
    cudaGetSymbolAddress((void**)&cs, g_cs);
    cudaGetSymbolAddress((void**)&Wqs, g_Wqs);
    cudaGetSymbolAddress((void**)&Wkvs, g_Wkvs);
    cudaGetSymbolAddress((void**)&Wos, g_Wos);

    cudaFuncSetAttribute(gemm_mma, cudaFuncAttributeMaxDynamicSharedMemorySize, GSMEM);
    cudaFuncSetAttribute(flash_kernel, cudaFuncAttributeMaxDynamicSharedMemorySize, FLASH_SMEM);

    // split conversions
    split_act<<<(MROWS * 512 + 255) / 256, 256>>>(x, xs, MROWS * 512);
    split_wt<<<dim3(DMODEL / 32, K2 / 32), dim3(32, 8)>>>(Wq, Wqs, DMODEL, 0);
    split_wt<<<dim3(512 / 32, K2 / 32), dim3(32, 8)>>>(Wk, Wkvs, 512, 0);
    split_wt<<<dim3(512 / 32, K2 / 32), dim3(32, 8)>>>(Wv, Wkvs, 512, 512);
    split_wt<<<dim3(DMODEL / 32, K2 / 32), dim3(32, 8)>>>(Wo, Wos, DMODEL, 0);

    // Q and merged K|V projections (tensor-core bf16x3)
    gemm_mma<<<dim3(DMODEL / 128, MROWS / 128), 256, GSMEM>>>(xs, Wqs, nullptr, Qb, DMODEL);
    gemm_mma<<<dim3(KVW / 128, MROWS / 128), 256, GSMEM>>>(xs, Wkvs, nullptr, KVb, KVW);

    // attention
    flash_kernel<<<dim3(NSEQ / 64, NHEADS, BATCH), 256, FLASH_SMEM>>>(Qb, KVb, Cb);

    // output projection
    split_act<<<(MROWS * 512 + 255) / 256, 256>>>(Cb, cs, MROWS * 512);
    gemm_mma<<<dim3(DMODEL / 128, MROWS / 128), 256, GSMEM>>>(cs, Wos, bo, out, DMODEL);
}

// round 6
// speedup vs baseline: 4.0387x; 2.5639x over previous
#include <cuda_runtime.h>
#include <cuda_bf16.h>
#include <math.h>
#include <stdint.h>

// ---------------- problem constants ----------------
#define BATCH   2
#define NSEQ    2048
#define DMODEL  2048
#define KVW     1024
#define NHEADS  16
#define HDIM    128
#define MROWS   4096
#define K2      2048
#define KX      6144          // split inner dim (hi | lo | hi)
#define NCH     (KX / 64)     // 96 K-chunks of 64

// ---------------- scratch (device globals) ----------------
__device__ __nv_bfloat16 g_xs[(size_t)MROWS * KX];
__device__ __nv_bfloat16 g_cs[(size_t)MROWS * KX];
__device__ __nv_bfloat16 g_Wqs[(size_t)DMODEL * KX];
__device__ __nv_bfloat16 g_Wkvs[(size_t)KVW * KX];
__device__ __nv_bfloat16 g_Wos[(size_t)DMODEL * KX];
__device__ __nv_bfloat16 g_Qh[(size_t)MROWS * DMODEL];
__device__ __nv_bfloat16 g_Ql[(size_t)MROWS * DMODEL];
__device__ __nv_bfloat16 g_KVh[(size_t)MROWS * KVW];
__device__ __nv_bfloat16 g_KVl[(size_t)MROWS * KVW];

// ---------------- helpers ----------------
__device__ __forceinline__ uint32_t smem_u32(const void* p) {
    uint32_t a;
    asm("{ .reg .u64 t; cvta.to.shared.u64 t, %1; cvt.u32.u64 %0, t; }" : "=r"(a) : "l"(p));
    return a;
}
__device__ __forceinline__ void cp16(uint32_t dst, const void* src) {
    asm volatile("cp.async.cg.shared.global [%0], [%1], 16;" :: "r"(dst), "l"(src));
}
#define CP_COMMIT() asm volatile("cp.async.commit_group;" ::: "memory")

__device__ __forceinline__ void ldmat4(uint32_t* r, uint32_t addr) {
    asm volatile("ldmatrix.sync.aligned.m8n8.x4.shared.b16 {%0,%1,%2,%3}, [%4];"
                 : "=r"(r[0]), "=r"(r[1]), "=r"(r[2]), "=r"(r[3]) : "r"(addr));
}
__device__ __forceinline__ void ldmat4t(uint32_t* r, uint32_t addr) {
    asm volatile("ldmatrix.sync.aligned.m8n8.x4.trans.shared.b16 {%0,%1,%2,%3}, [%4];"
                 : "=r"(r[0]), "=r"(r[1]), "=r"(r[2]), "=r"(r[3]) : "r"(addr));
}
__device__ __forceinline__ void mma16816(float* d, const uint32_t* a, const uint32_t* b) {
    asm volatile("mma.sync.aligned.m16n8k16.row.col.f32.bf16.bf16.f32 "
                 "{%0,%1,%2,%3}, {%4,%5,%6,%7}, {%8,%9}, {%0,%1,%2,%3};"
                 : "+f"(d[0]), "+f"(d[1]), "+f"(d[2]), "+f"(d[3])
                 : "r"(a[0]), "r"(a[1]), "r"(a[2]), "r"(a[3]), "r"(b[0]), "r"(b[1]));
}
// split v0,v1 into bf16x2 (hi) and bf16x2 (residual lo); lower half = v0
__device__ __forceinline__ void split2(float v0, float v1, uint32_t& hi, uint32_t& lo) {
    __nv_bfloat16 h0 = __float2bfloat16(v0), h1 = __float2bfloat16(v1);
    __nv_bfloat16 l0 = __float2bfloat16(v0 - __bfloat162float(h0));
    __nv_bfloat16 l1 = __float2bfloat16(v1 - __bfloat162float(h1));
    __nv_bfloat162 H(h0, h1), L(l0, l1);
    hi = *(uint32_t*)&H; lo = *(uint32_t*)&L;
}

// ---------------------------------------------------------------------------
// Split conversion kernels
// ---------------------------------------------------------------------------
__global__ void split_act(const float* __restrict__ src, __nv_bfloat16* __restrict__ dst,
                          int total4)
{
    int i = blockIdx.x * 256 + threadIdx.x;
    if (i >= total4) return;
    int m = i >> 9;
    int c = (i & 511) << 2;
    float4 v = *(const float4*)&src[(size_t)m * K2 + c];
    __nv_bfloat16 h0 = __float2bfloat16(v.x), h1 = __float2bfloat16(v.y);
    __nv_bfloat16 h2 = __float2bfloat16(v.z), h3 = __float2bfloat16(v.w);
    __nv_bfloat16 l0 = __float2bfloat16(v.x - __bfloat162float(h0));
    __nv_bfloat16 l1 = __float2bfloat16(v.y - __bfloat162float(h1));
    __nv_bfloat16 l2 = __float2bfloat16(v.z - __bfloat162float(h2));
    __nv_bfloat16 l3 = __float2bfloat16(v.w - __bfloat162float(h3));
    __nv_bfloat162 hA(h0, h1), hB(h2, h3), lA(l0, l1), lB(l2, l3);
    __nv_bfloat162* p0 = (__nv_bfloat162*)&dst[(size_t)m * KX + c];
    __nv_bfloat162* p1 = (__nv_bfloat162*)&dst[(size_t)m * KX + K2 + c];
    __nv_bfloat162* p2 = (__nv_bfloat162*)&dst[(size_t)m * KX + 2 * K2 + c];
    p0[0] = hA; p0[1] = hB;
    p1[0] = lA; p1[1] = lB;
    p2[0] = hA; p2[1] = hB;
}

__global__ void split_wt(const float* __restrict__ W, __nv_bfloat16* __restrict__ dst,
                         int N, int rowoff)
{
    __shared__ float tile[32][33];
    int n0 = blockIdx.x * 32, k0 = blockIdx.y * 32;
    int tx = threadIdx.x, ty = threadIdx.y;
#pragma unroll
    for (int j = 0; j < 32; j += 8)
        tile[ty + j][tx] = W[(size_t)(k0 + ty + j) * N + n0 + tx];
    __syncthreads();
#pragma unroll
    for (int j = 0; j < 32; j += 8) {
        int n = n0 + ty + j;
        int k = k0 + tx;
        float v = tile[tx][ty + j];
        __nv_bfloat16 hi = __float2bfloat16(v);
        __nv_bfloat16 lo = __float2bfloat16(v - __bfloat162float(hi));
        size_t base = (size_t)(rowoff + n) * KX;
        dst[base + k]          = hi;
        dst[base + K2 + k]     = hi;
        dst[base + 2 * K2 + k] = lo;
    }
}

// ---------------------------------------------------------------------------
// bf16 GEMM via mma.sync, CTA 128x128, BK=64, 3-stage cp.async.
// Epilogue: fp32 C (+bias)  OR  split bf16 hi/lo pair (scaled).
// ---------------------------------------------------------------------------
#define STAGE_BYTES 32768
#define GSMEM (3 * STAGE_BYTES)

__global__ void __launch_bounds__(256)
gemm_mma(const __nv_bfloat16* __restrict__ A, const __nv_bfloat16* __restrict__ B,
         const float* __restrict__ bias, float* __restrict__ C,
         __nv_bfloat16* __restrict__ Hout, __nv_bfloat16* __restrict__ Lout,
         int Nt, float oscale)
{
    extern __shared__ char sm[];
    const uint32_t sb = smem_u32(sm);
    const int tid = threadIdx.x;
    const int warp = tid >> 5, lane = tid & 31;
    const int wm = warp >> 1;
    const int wn = warp & 1;
    const int bm0 = blockIdx.y * 128;
    const int bn0 = blockIdx.x * 128;

    const __nv_bfloat16* Ab = A + (size_t)bm0 * KX;
    const __nv_bfloat16* Bb = B + (size_t)bn0 * KX;

    const int a_row0 = wm * 32 + (lane & 15);
    const uint32_t a_half = (uint32_t)((lane >> 4) << 4);
    const uint32_t a_xr = (uint32_t)((a_row0 & 7) << 4);
    uint32_t a_rb[2];
    a_rb[0] = (uint32_t)(a_row0 * 128);
    a_rb[1] = (uint32_t)((a_row0 + 16) * 128);

    const int b_row0 = wn * 64 + (lane & 7) + ((lane >> 4) << 3);
    const uint32_t b_half = (uint32_t)(((lane >> 3) & 1) << 4);
    const uint32_t b_xr = (uint32_t)((b_row0 & 7) << 4);
    uint32_t b_rb[4];
#pragma unroll
    for (int p = 0; p < 4; p++) b_rb[p] = (uint32_t)((b_row0 + p * 16) * 128);

    float acc[2][8][4];
#pragma unroll
    for (int mf = 0; mf < 2; mf++)
#pragma unroll
        for (int nf = 0; nf < 8; nf++)
#pragma unroll
            for (int j = 0; j < 4; j++) acc[mf][nf][j] = 0.f;

    auto load_stage = [&](int s, int kc) {
        uint32_t abase = sb + (uint32_t)s * STAGE_BYTES;
        uint32_t bbase = abase + 16384;
        const __nv_bfloat16* ak = Ab + (size_t)kc * 64;
        const __nv_bfloat16* bk = Bb + (size_t)kc * 64;
#pragma unroll
        for (int c = tid; c < 1024; c += 256) {
            int r = c >> 3, sg = c & 7;
            uint32_t off = (uint32_t)(r * 128 + sg * 16);
            uint32_t sw = off ^ ((off >> 3) & 0x70);
            cp16(abase + sw, (const void*)(ak + (size_t)r * KX + sg * 8));
            cp16(bbase + sw, (const void*)(bk + (size_t)r * KX + sg * 8));
        }
        CP_COMMIT();
    };

    load_stage(0, 0);
    load_stage(1, 1);

    for (int i = 0; i < NCH; i++) {
        const int s = i % 3;
        if (i + 2 < NCH) {
            load_stage((i + 2) % 3, i + 2);
            asm volatile("cp.async.wait_group 2;" ::: "memory");
        } else if (i + 2 == NCH) {
            asm volatile("cp.async.wait_group 1;" ::: "memory");
        } else {
            asm volatile("cp.async.wait_group 0;" ::: "memory");
        }
        __syncthreads();

        const uint32_t abase = sb + (uint32_t)s * STAGE_BYTES;
        const uint32_t bbase = abase + 16384;
#pragma unroll
        for (int ks = 0; ks < 4; ks++) {
            uint32_t afrag[2][4];
            uint32_t bfrag[8][2];
#pragma unroll
            for (int mf = 0; mf < 2; mf++)
                ldmat4(afrag[mf], abase + a_rb[mf] + (((uint32_t)(ks * 32) + a_half) ^ a_xr));
#pragma unroll
            for (int p = 0; p < 4; p++) {
                uint32_t r4[4];
                ldmat4(r4, bbase + b_rb[p] + (((uint32_t)(ks * 32) + b_half) ^ b_xr));
                bfrag[2 * p][0] = r4[0]; bfrag[2 * p][1] = r4[1];
                bfrag[2 * p + 1][0] = r4[2]; bfrag[2 * p + 1][1] = r4[3];
            }
#pragma unroll
            for (int mf = 0; mf < 2; mf++)
#pragma unroll
                for (int nf = 0; nf < 8; nf++)
                    mma16816(acc[mf][nf], afrag[mf], bfrag[nf]);
        }
        __syncthreads();
    }

    const int m_base = bm0 + wm * 32;
    const int n_base = bn0 + wn * 64;
    const int rl = lane >> 2;
    const int cl = (lane & 3) * 2;
    if (Hout) {
#pragma unroll
        for (int mf = 0; mf < 2; mf++) {
#pragma unroll
            for (int nf = 0; nf < 8; nf++) {
                int col = n_base + nf * 8 + cl;
                int r0 = m_base + mf * 16 + rl;
                uint32_t h0, l0, h1, l1;
                split2(acc[mf][nf][0] * oscale, acc[mf][nf][1] * oscale, h0, l0);
                split2(acc[mf][nf][2] * oscale, acc[mf][nf][3] * oscale, h1, l1);
                *(uint32_t*)&Hout[(size_t)r0 * Nt + col] = h0;
                *(uint32_t*)&Lout[(size_t)r0 * Nt + col] = l0;
                *(uint32_t*)&Hout[(size_t)(r0 + 8) * Nt + col] = h1;
                *(uint32_t*)&Lout[(size_t)(r0 + 8) * Nt + col] = l1;
            }
        }
    } else {
#pragma unroll
        for (int mf = 0; mf < 2; mf++) {
#pragma unroll
            for (int nf = 0; nf < 8; nf++) {
                int col = n_base + nf * 8 + cl;
                float b0 = 0.f, b1 = 0.f;
                if (bias) { b0 = bias[col]; b1 = bias[col + 1]; }
                int r0 = m_base + mf * 16 + rl;
                float2 v0 = make_float2(acc[mf][nf][0] + b0, acc[mf][nf][1] + b1);
                float2 v1 = make_float2(acc[mf][nf][2] + b0, acc[mf][nf][3] + b1);
                *(float2*)&C[(size_t)r0 * Nt + col] = v0;
                *(float2*)&C[(size_t)(r0 + 8) * Nt + col] = v1;
            }
        }
    }
}

// ---------------------------------------------------------------------------
// Tensor-core causal flash attention, split-bf16 precision.
// Br=128 (8 warps x 16 rows), Bc=64, d=128. Writes ctx in split [hi|lo|hi].
// ---------------------------------------------------------------------------
#define PITCHB 272              // bytes per smem row (136 halves)
#define FQH 0
#define FQL 34816
#define FKV0 69632
#define FKVBUF 69632            // per double-buffer: KH,KL,VH,VL each 17408
#define FTILE 17408
#define FSMEM 208896

__global__ void __launch_bounds__(256, 1)
flash_tc(const __nv_bfloat16* __restrict__ Qh, const __nv_bfloat16* __restrict__ Ql,
         const __nv_bfloat16* __restrict__ KVh, const __nv_bfloat16* __restrict__ KVl,
         __nv_bfloat16* __restrict__ cs)
{
    extern __shared__ char sm[];
    const uint32_t sb = smem_u32(sm);
    const int tid = threadIdx.x;
    const int warp = tid >> 5, lane = tid & 31;
    const int jr = 15 - blockIdx.x;          // heavy tiles first
    const int h = blockIdx.y;
    const int b = blockIdx.z;
    const int g = h >> 2;
    const int qr0 = jr * 128;
    const int nct = 2 * jr + 2;

    // ---- load Q hi/lo tiles (128 x 128 halves each) ----
    {
        const __nv_bfloat16* qhb = Qh + ((size_t)(b * NSEQ + qr0)) * DMODEL + h * HDIM;
        const __nv_bfloat16* qlb = Ql + ((size_t)(b * NSEQ + qr0)) * DMODEL + h * HDIM;
        for (int c = tid; c < 2048; c += 256) {
            int r = c >> 4, sg = c & 15;
            uint32_t soff = (uint32_t)(r * PITCHB + sg * 16);
            cp16(sb + FQH + soff, (const void*)(qhb + (size_t)r * DMODEL + sg * 8));
            cp16(sb + FQL + soff, (const void*)(qlb + (size_t)r * DMODEL + sg * 8));
        }
    }
    // ---- prefetch KV tile 0 into buffer 0 ----
    auto load_kv = [&](int bufi, int ct) {
        uint32_t base = sb + FKV0 + (uint32_t)bufi * FKVBUF;
        size_t grow0 = (size_t)(b * NSEQ + ct * 64);
        for (int c = tid; c < 1024; c += 256) {
            int r = c >> 4, sg = c & 15;
            uint32_t soff = (uint32_t)(r * PITCHB + sg * 16);
            size_t gk = (grow0 + r) * KVW + g * HDIM + sg * 8;
            size_t gv = gk + 512;
            cp16(base + 0 * FTILE + soff, (const void*)(KVh + gk));
            cp16(base + 1 * FTILE + soff, (const void*)(KVl + gk));
            cp16(base + 2 * FTILE + soff, (const void*)(KVh + gv));
            cp16(base + 3 * FTILE + soff, (const void*)(KVl + gv));
        }
    };
    load_kv(0, 0);
    CP_COMMIT();

    // per-warp/lane addressing
    const uint32_t a_off = (uint32_t)((warp * 16 + (lane & 15)) * PITCHB + ((lane >> 4) << 4));
    const uint32_t bk_off = (uint32_t)(((lane & 7) + ((lane >> 4) << 3)) * PITCHB +
                                       (((lane >> 3) & 1) << 4));
    const uint32_t v_off = (uint32_t)((lane & 15) * PITCHB + ((lane >> 4) << 4));

    float O[16][4];
#pragma unroll
    for (int f = 0; f < 16; f++)
#pragma unroll
        for (int j = 0; j < 4; j++) O[f][j] = 0.f;
    float m0 = -INFINITY, m1 = -INFINITY, l0 = 0.f, l1 = 0.f;

    const int row0g = qr0 + warp * 16 + (lane >> 2);   // global q row (and +8)

    for (int ct = 0; ct < nct; ct++) {
        asm volatile("cp.async.wait_group 0;" ::: "memory");
        __syncthreads();
        if (ct + 1 < nct) { load_kv((ct + 1) & 1, ct + 1); CP_COMMIT(); }

        const uint32_t kvb = sb + FKV0 + (uint32_t)(ct & 1) * FKVBUF;
        const uint32_t KH = kvb, KL = kvb + FTILE, VH = kvb + 2 * FTILE, VL = kvb + 3 * FTILE;
        const int kc0 = ct * 64;

        // ---- S = Q K^T (split bf16, 3 chains) ----
        float S[8][4];
#pragma unroll
        for (int f = 0; f < 8; f++)
#pragma unroll
            for (int j = 0; j < 4; j++) S[f][j] = 0.f;

#pragma unroll
        for (int ks = 0; ks < 8; ks++) {
            uint32_t qh4[4], ql4[4];
            ldmat4(qh4, sb + FQH + a_off + ks * 32);
            ldmat4(ql4, sb + FQL + a_off + ks * 32);
#pragma unroll
            for (int p = 0; p < 4; p++) {
                uint32_t kh4[4], kl4[4];
                ldmat4(kh4, KH + bk_off + (uint32_t)(p * 16 * PITCHB) + ks * 32);
                ldmat4(kl4, KL + bk_off + (uint32_t)(p * 16 * PITCHB) + ks * 32);
                mma16816(S[2 * p], qh4, kh4);
                mma16816(S[2 * p], ql4, kh4);
                mma16816(S[2 * p], qh4, kl4);
                mma16816(S[2 * p + 1], qh4, kh4 + 2);
                mma16816(S[2 * p + 1], ql4, kh4 + 2);
                mma16816(S[2 * p + 1], qh4, kl4 + 2);
            }
        }

        // ---- causal mask (only the two diagonal tiles) ----
        if (ct >= nct - 2) {
#pragma unroll
            for (int f = 0; f < 8; f++) {
                int colb = kc0 + f * 8 + 2 * (lane & 3);
#pragma unroll
                for (int j = 0; j < 4; j++) {
                    int col = colb + (j & 1);
                    int row = row0g + ((j >> 1) << 3);
                    if (col > row) S[f][j] = -INFINITY;
                }
            }
        }

        // ---- online softmax ----
        float mx0 = -INFINITY, mx1 = -INFINITY;
#pragma unroll
        for (int f = 0; f < 8; f++) {
            mx0 = fmaxf(mx0, fmaxf(S[f][0], S[f][1]));
            mx1 = fmaxf(mx1, fmaxf(S[f][2], S[f][3]));
        }
        mx0 = fmaxf(mx0, __shfl_xor_sync(0xffffffffu, mx0, 1));
        mx0 = fmaxf(mx0, __shfl_xor_sync(0xffffffffu, mx0, 2));
        mx1 = fmaxf(mx1, __shfl_xor_sync(0xffffffffu, mx1, 1));
        mx1 = fmaxf(mx1, __shfl_xor_sync(0xffffffffu, mx1, 2));
        float mn0 = fmaxf(m0, mx0), mn1 = fmaxf(m1, mx1);
        float al0 = __expf(m0 - mn0), al1 = __expf(m1 - mn1);
        float rs0 = 0.f, rs1 = 0.f;
#pragma unroll
        for (int f = 0; f < 8; f++) {
            S[f][0] = __expf(S[f][0] - mn0); S[f][1] = __expf(S[f][1] - mn0);
            S[f][2] = __expf(S[f][2] - mn1); S[f][3] = __expf(S[f][3] - mn1);
            rs0 += S[f][0] + S[f][1];
            rs1 += S[f][2] + S[f][3];
        }
        rs0 += __shfl_xor_sync(0xffffffffu, rs0, 1);
        rs0 += __shfl_xor_sync(0xffffffffu, rs0, 2);
        rs1 += __shfl_xor_sync(0xffffffffu, rs1, 1);
        rs1 += __shfl_xor_sync(0xffffffffu, rs1, 2);
        l0 = l0 * al0 + rs0; l1 = l1 * al1 + rs1;
        m0 = mn0; m1 = mn1;
#pragma unroll
        for (int f = 0; f < 16; f++) {
            O[f][0] *= al0; O[f][1] *= al0;
            O[f][2] *= al1; O[f][3] *= al1;
        }

        // ---- P fragments (hi + residual lo) ----
        uint32_t pf[4][4], pl[4][4];
#pragma unroll
        for (int t = 0; t < 4; t++) {
            split2(S[2 * t][0], S[2 * t][1], pf[t][0], pl[t][0]);
            split2(S[2 * t][2], S[2 * t][3], pf[t][1], pl[t][1]);
            split2(S[2 * t + 1][0], S[2 * t + 1][1], pf[t][2], pl[t][2]);
            split2(S[2 * t + 1][2], S[2 * t + 1][3], pf[t][3], pl[t][3]);
        }

        // ---- O += P V (split bf16, 3 chains), V via ldmatrix.trans ----
#pragma unroll
        for (int t = 0; t < 4; t++) {
#pragma unroll
            for (int q = 0; q < 8; q++) {
                uint32_t vh4[4], vl4[4];
                ldmat4t(vh4, VH + v_off + (uint32_t)(t * 16 * PITCHB) + q * 32);
                ldmat4t(vl4, VL + v_off + (uint32_t)(t * 16 * PITCHB) + q * 32);
                mma16816(O[2 * q], pf[t], vh4);
                mma16816(O[2 * q], pl[t], vh4);
                mma16816(O[2 * q], pf[t], vl4);
                mma16816(O[2 * q + 1], pf[t], vh4 + 2);
                mma16816(O[2 * q + 1], pl[t], vh4 + 2);
                mma16816(O[2 * q + 1], pf[t], vl4 + 2);
            }
        }
    }

    // ---- epilogue: normalize and write split ctx [hi | lo | hi] ----
    float inv0 = 1.f / l0, inv1 = 1.f / l1;
    size_t row0 = (size_t)(b * NSEQ) + qr0 + warp * 16 + (lane >> 2);
    __nv_bfloat16* base0 = cs + row0 * KX;
    __nv_bfloat16* base1 = cs + (row0 + 8) * KX;
    int colb = h * HDIM + 2 * (lane & 3);
#pragma unroll
    for (int f = 0; f < 16; f++) {
        int col = colb + f * 8;
        uint32_t h0, lo0, h1, lo1;
        split2(O[f][0] * inv0, O[f][1] * inv0, h0, lo0);
        split2(O[f][2] * inv1, O[f][3] * inv1, h1, lo1);
        *(uint32_t*)&base0[col] = h0;
        *(uint32_t*)&base0[K2 + col] = lo0;
        *(uint32_t*)&base0[2 * K2 + col] = h0;
        *(uint32_t*)&base1[col] = h1;
        *(uint32_t*)&base1[K2 + col] = lo1;
        *(uint32_t*)&base1[2 * K2 + col] = h1;
    }
}

// ---------------------------------------------------------------------------
extern "C" void kernel_launch(void* const* d_in, const int* in_sizes, int n_in,
                              void* d_out, int out_size)
{
    (void)in_sizes; (void)n_in; (void)out_size;
    const float* x  = (const float*)d_in[0];
    const float* Wq = (const float*)d_in[1];
    const float* Wk = (const float*)d_in[2];
    const float* Wv = (const float*)d_in[3];
    const float* Wo = (const float*)d_in[4];
    const float* bo = (const float*)d_in[5];
    float* out = (float*)d_out;

    __nv_bfloat16 *xs, *cs, *Wqs, *Wkvs, *Wos, *Qh, *Ql, *KVh, *KVl;
    cudaGetSymbolAddress((void**)&xs, g_xs);
    cudaGetSymbolAddress((void**)&cs, g_cs);
    cudaGetSymbolAddress((void**)&Wqs, g_Wqs);
    cudaGetSymbolAddress((void**)&Wkvs, g_Wkvs);
    cudaGetSymbolAddress((void**)&Wos, g_Wos);
    cudaGetSymbolAddress((void**)&Qh, g_Qh);
    cudaGetSymbolAddress((void**)&Ql, g_Ql);
    cudaGetSymbolAddress((void**)&KVh, g_KVh);
    cudaGetSymbolAddress((void**)&KVl, g_KVl);

    cudaFuncSetAttribute(gemm_mma, cudaFuncAttributeMaxDynamicSharedMemorySize, GSMEM);
    cudaFuncSetAttribute(flash_tc, cudaFuncAttributeMaxDynamicSharedMemorySize, FSMEM);

    // input/weight splits
    split_act<<<(MROWS * 512 + 255) / 256, 256>>>(x, xs, MROWS * 512);
    split_wt<<<dim3(DMODEL / 32, K2 / 32), dim3(32, 8)>>>(Wq, Wqs, DMODEL, 0);
    split_wt<<<dim3(512 / 32, K2 / 32), dim3(32, 8)>>>(Wk, Wkvs, 512, 0);
    split_wt<<<dim3(512 / 32, K2 / 32), dim3(32, 8)>>>(Wv, Wkvs, 512, 512);
    split_wt<<<dim3(DMODEL / 32, K2 / 32), dim3(32, 8)>>>(Wo, Wos, DMODEL, 0);

    // projections -> pre-split bf16 (Q pre-scaled by 1/sqrt(d))
    gemm_mma<<<dim3(DMODEL / 128, MROWS / 128), 256, GSMEM>>>(
        xs, Wqs, nullptr, nullptr, Qh, Ql, DMODEL, 0.08838834764831845f);
    gemm_mma<<<dim3(KVW / 128, MROWS / 128), 256, GSMEM>>>(
        xs, Wkvs, nullptr, nullptr, KVh, KVl, KVW, 1.0f);

    // tensor-core flash attention -> split ctx
    flash_tc<<<dim3(16, NHEADS, BATCH), 256, FSMEM>>>(Qh, Ql, KVh, KVl, cs);

    // output projection + bias
    gemm_mma<<<dim3(DMODEL / 128, MROWS / 128), 256, GSMEM>>>(
        cs, Wos, bo, out, nullptr, nullptr, DMODEL, 1.0f);
}